// round 1
// baseline (speedup 1.0000x reference)
#include <cuda_runtime.h>

#define T_LEN 2048

__device__ __forceinline__ float tanh_fast(float x) {
    float y;
    asm("tanh.approx.f32 %0, %1;" : "=f"(y) : "f"(x));
    return y;
}

// heaviside(x) given arg10 = 10*x :  (tanh(10x)+1)*0.5
__device__ __forceinline__ float heav10(float arg10) {
    return fmaf(tanh_fast(arg10), 0.5f, 0.5f);
}

__device__ __forceinline__ float clipf(float v) {
    return fminf(fmaxf(v, -100000.0f), 100000.0f);
}

__global__ void __launch_bounds__(32, 1) xaj_kernel(
    const float* __restrict__ inputs,
    const float* __restrict__ pwum, const float* __restrict__ pwlm,
    const float* __restrict__ pwdm, const float* __restrict__ pc,
    const float* __restrict__ pb,  const float* __restrict__ pk1,
    const float* __restrict__ pk2, const float* __restrict__ pk3,
    float* __restrict__ out, int B)
{
    const int b = blockIdx.x * blockDim.x + threadIdx.x;
    if (b >= B) return;

    // --- scalar parameter preprocessing (note the arg swaps in the reference
    // call: runoff_production(wu, wd, wl, p, wum, wdm, wlm, b, c)) ---
    const float wum_p = pwum[0] * 19.9f + 0.1f;
    const float wlm_p = pwdm[0] * 30.0f + 60.0f;   // wlm slot receives wdm input
    const float wdm_p = pwlm[0] * 60.0f + 60.0f;   // wdm slot receives wlm input
    const float W     = wum_p + wlm_p + wdm_p;
    const float invW  = 1.0f / W;
    const float c2 = pc[0] * 0.19f + 0.01f;
    const float b2 = pb[0] * 0.30f + 0.10f;
    const float k1 = pk1[0] * 0.69f + 0.01f;
    const float k2 = pk2[0] * 0.69f + 0.01f;
    const float k3 = pk3[0] * 0.89f + 0.01f;
    // q = surface + 0.5*inter + 0.25*base = F * runoff
    const float F = k1 + 0.5f * k2 * (1.0f - k1)
                  + 0.25f * k3 * (1.0f - k2) * (1.0f - k1);

    const float4* __restrict__ in4 =
        reinterpret_cast<const float4*>(inputs + (size_t)b * (T_LEN * 3));
    float4* __restrict__ out4 =
        reinterpret_cast<float4*>(out + (size_t)b * T_LEN);

    float wu = 0.0f, wl = 0.0f, wd = 0.0f;
    float wu10 = 0.0f, wl10 = 0.0f, wd10 = 0.0f;

    const int NG = T_LEN / 4;
    float4 A = in4[0], Bv = in4[1], C = in4[2];

    #pragma unroll 2
    for (int g = 0; g < NG; ++g) {
        // prefetch next group (redundant reload of last group is harmless)
        const int gn = (g + 1 < NG) ? (g + 1) : g;
        const float4 nA = in4[gn * 3 + 0];
        const float4 nB = in4[gn * 3 + 1];
        const float4 nC = in4[gn * 3 + 2];

        // (B,T,3) layout: pet = ch0, p = ch2
        const float pet_[4] = { A.x, A.w, Bv.z, C.y };
        const float pp_[4]  = { A.z, Bv.y, C.x, C.w };
        float qv[4];

        #pragma unroll
        for (int i = 0; i < 4; ++i) {
            const float pet = pet_[i];
            const float p   = pp_[i];

            // --- evapotranspiration ---
            // et1 = h1*pet + (1-h1)*wu,  h1 = H(wu - pet)
            const float h1  = heav10(wu10 - 10.0f * pet);
            const float et1 = fmaf(h1, pet - wu, wu);

            // rem = H(pet - et1) * (pet - et1)
            const float rem_raw = pet - et1;
            const float hr  = heav10(10.0f * rem_raw);
            const float rem = hr * rem_raw;
            const float rem10 = 10.0f * rem;

            // et22 = h2*wl + (1-h2)*rem,  h2 = H(rem - wl)
            const float h2   = heav10(rem10 - wl10);
            const float et22 = fmaf(h2, wl - rem, rem);
            // et2 = H(rem) * et22
            const float h3  = heav10(rem10);
            const float et2 = h3 * et22;

            const float x   = rem - et2;
            const float x10 = 10.0f * x;
            // et33 = h4*wd + (1-h4)*x,  h4 = H(x - wd)
            const float h4   = heav10(x10 - wd10);
            const float et33 = fmaf(h4, wd - x, x);
            // et3 = H(x) * et33
            const float h5  = heav10(x10);
            const float et3 = h5 * et33;

            // --- state update (traj stores the NEW state) ---
            const float d1 = p - et1;
            wu = wu + clipf(d1);
            const float d2 = d1 - et2;
            wl = wl + clipf(d2);
            const float d3 = d2 - et3;
            wd = wd + clipf(d3);
            wu10 = 10.0f * wu;
            wl10 = 10.0f * wl;
            wd10 = 10.0f * wd;

            // --- runoff + partition + routing (fused, off the carried chain) ---
            const float u = wu * invW;
            const float v = wd * invW;
            const float s = fmaf(c2, u * u, b2 * (v * v));
            const float dd = p - s;
            const float hR = heav10(10.0f * dd);
            qv[i] = F * hR * dd;
        }

        out4[g] = make_float4(qv[0], qv[1], qv[2], qv[3]);

        A = nA; Bv = nB; C = nC;
    }
}

extern "C" void kernel_launch(void* const* d_in, const int* in_sizes, int n_in,
                              void* d_out, int out_size) {
    const float* inputs = (const float*)d_in[0];
    const float* wum = (const float*)d_in[1];
    const float* wlm = (const float*)d_in[2];
    const float* wdm = (const float*)d_in[3];
    const float* c   = (const float*)d_in[4];
    const float* bb  = (const float*)d_in[5];
    const float* k1  = (const float*)d_in[6];
    const float* k2  = (const float*)d_in[7];
    const float* k3  = (const float*)d_in[8];
    float* out = (float*)d_out;

    const int B = in_sizes[0] / (T_LEN * 3);

    dim3 block(32);
    dim3 grid((B + 31) / 32);
    xaj_kernel<<<grid, block>>>(inputs, wum, wlm, wdm, c, bb, k1, k2, k3, out, B);
}